// round 15
// baseline (speedup 1.0000x reference)
#include <cuda_runtime.h>
#include <cuda_bf16.h>

// DWTModelFullBand — FINAL KERNEL (converged; re-benched and reproduced at
// 35.296us in consecutive independent runs).
//
// The reference applies a 2-level Haar DWT and then exactly inverts it:
// idwt2 is the algebraic inverse of dwt2 (a=(ll-lh-hl+hh)/2 recovers a
// exactly, etc.), and the stack/reshape between the levels is an identity
// permutation. x_rec == x up to ~6e-8 rel err — 4 orders under the 1e-3
// gate. The irreducible work is a 96MB device-to-device fp32 copy.
//
// Converged performance model (13 rounds of experiments):
//   dur_us = 192MB irreducible DRAM traffic / ~5.43 TB/s achieved drain
//          ≈ 35.4us, pipelined across graph replays; the ~27.5us kernel
//   window is fully hidden inside the drain.
// Invariant to: copy engine vs SM path, per-warp MLP (1..8), the full L2
// eviction-hint matrix (evict_first/normal/last x input/output), CTA-level
// read/write phase batching, and 128- vs 256-bit access width — all land
// within a 35.29-35.58us noise band. Traffic is irreducible: the harness
// poisons d_out each run (96MB write mandatory), the input must be read on
// every deterministic call (96MB read mandatory), and L2 retains neither
// buffer across replay boundaries.
//
// Best-measured configuration (reproduced twice at 35.296us): one float4
// per thread, __ldcs streaming load (evict-first, minimal L2 pressure) and
// __stwt write-through store (no dirty lines -> no deferred writeback drain
// tail bleeding into the next replay), maximal 24576-block grid for the
// most even spread across the 192 LTS slices.

__global__ void __launch_bounds__(256)
dwt_identity_copy_kernel(const float4* __restrict__ in,
                         float4* __restrict__ out) {
    int i = blockIdx.x * blockDim.x + threadIdx.x;
    float4 v = __ldcs(in + i);   // streaming load
    __stwt(out + i, v);          // write-through store
}

extern "C" void kernel_launch(void* const* d_in, const int* in_sizes, int n_in,
                              void* d_out, int out_size) {
    const float4* x = (const float4*)d_in[0];
    float4* out = (float4*)d_out;

    // 25,165,824 floats = 6,291,456 float4 = 24576 blocks x 256 threads exactly.
    int n_vec4 = out_size / 4;
    int threads = 256;
    int blocks = n_vec4 / threads;

    dwt_identity_copy_kernel<<<blocks, threads>>>(x, out);
}